// round 4
// baseline (speedup 1.0000x reference)
#include <cuda_runtime.h>
#include <stdint.h>

// LSTM: H=50, input dim 1, T=1024, B independent batch elements.
// One block (224 threads) per FOUR batch elements (M=4). Thread j (<200)
// owns gate row j — 26 packed f32x2 weight regs SHARED across the 4 batch
// elements — and runs 4 independent accumulator chains (one per batch).
// Per thread per step: 52 broadcast LDS.128 + 104 fma.rn.f32x2.
// Phase 2: thread j (<200) updates c/h for (batch j/50, hidden j%50).
// 2 __syncthreads per step, amortized over 4x the work of the R1 kernel.
// Gate order (PyTorch): i[0:50], f[50:100], g[100:150], o[150:200].

#define HH 50
#define GG 200
#define TT 1024
#define BT 224
#define MM 4          // batch elements per block
#define KP 52         // H padded to multiple of 4

typedef unsigned long long ull;

__device__ __forceinline__ float sigf(float x) {
    return 1.0f / (1.0f + __expf(-x));
}
__device__ __forceinline__ float tanhfast(float x) {
    return fmaf(2.0f, sigf(2.0f * x), -1.0f);
}
__device__ __forceinline__ void fma2(ull& d, ull a, ull b) {
    asm("fma.rn.f32x2 %0, %1, %2, %0;" : "+l"(d) : "l"(a), "l"(b));
}
__device__ __forceinline__ ull pack2(float lo, float hi) {
    return ((ull)__float_as_uint(hi) << 32) | (ull)__float_as_uint(lo);
}
__device__ __forceinline__ float sum2(ull a) {
    return __uint_as_float((unsigned)a) + __uint_as_float((unsigned)(a >> 32));
}

__global__ void __launch_bounds__(BT, 3)
lstm_kernel(const float* __restrict__ x,      // [B, T, 1]
            const float* __restrict__ W_ih,   // [200, 1]
            const float* __restrict__ W_hh,   // [200, 50]
            const float* __restrict__ b_ih,   // [200]
            const float* __restrict__ b_hh,   // [200]
            const float* __restrict__ W_lin,  // [1, 50]
            const float* __restrict__ b_lin,  // [1]
            float* __restrict__ out,          // [B, 1]
            int B)
{
    __shared__ __align__(16) float h_sh[2][MM][KP];  // double-buffered h
    __shared__ float act_sh[MM][GG];
    __shared__ float x_sh[MM][TT];

    const int j  = threadIdx.x;
    const int b0 = blockIdx.x * MM;

    // Stage the 4 batch rows of x (zero-fill past B).
    for (int i = j; i < MM * TT; i += BT) {
        const int m = i >> 10, t = i & (TT - 1);
        x_sh[m][t] = (b0 + m < B) ? x[(size_t)(b0 + m) * TT + t] : 0.0f;
    }
    if (j < 2 * MM * KP) ((float*)h_sh)[j] = 0.0f;   // h0 = 0, pads stay 0

    float wih = 0.0f, bias = 0.0f;
    ull wp[KP / 2];
    if (j < GG) {
        wih  = W_ih[j];
        bias = b_ih[j] + b_hh[j];
        #pragma unroll
        for (int q = 0; q < KP / 2; q++) {
            float lo = (2 * q     < HH) ? W_hh[j * HH + 2 * q]     : 0.0f;
            float hi = (2 * q + 1 < HH) ? W_hh[j * HH + 2 * q + 1] : 0.0f;
            wp[q] = pack2(lo, hi);
        }
    }
    const bool gate_g = (j >= 100 && j < 150);
    // Phase-2 mapping: batch mu = j/50, hidden ku = j%50 (j < 200).
    const int mu = j / HH;
    const int ku = j - mu * HH;
    float c = 0.0f;

    __syncthreads();

    #pragma unroll 1
    for (int t = 0; t < TT; t++) {
        const int rb = t & 1;
        if (j < GG) {
            ull a0[MM], a1[MM];
            #pragma unroll
            for (int m = 0; m < MM; m++) {
                a0[m] = (ull)__float_as_uint(fmaf(x_sh[m][t], wih, bias));
                a1[m] = 0ull;
            }
            const ulonglong2* h2[MM];
            #pragma unroll
            for (int m = 0; m < MM; m++)
                h2[m] = (const ulonglong2*)h_sh[rb][m];
            #pragma unroll
            for (int q = 0; q < 13; q++) {
                #pragma unroll
                for (int m = 0; m < MM; m++) {
                    ulonglong2 hv = h2[m][q];          // broadcast LDS.128
                    fma2(a0[m], wp[2 * q],     hv.x);
                    fma2(a1[m], wp[2 * q + 1], hv.y);
                }
            }
            #pragma unroll
            for (int m = 0; m < MM; m++) {
                const float s = sum2(a0[m]) + sum2(a1[m]);
                act_sh[m][j] = gate_g ? tanhfast(s) : sigf(s);
            }
        }
        __syncthreads();
        if (j < GG) {
            const float gi = act_sh[mu][ku];
            const float gf = act_sh[mu][ku + 50];
            const float gg = act_sh[mu][ku + 100];
            const float go = act_sh[mu][ku + 150];
            c = fmaf(gf, c, gi * gg);
            h_sh[rb ^ 1][mu][ku] = go * tanhfast(c);
        }
        __syncthreads();
    }

    // Final h is in buffer (1023&1)^1 == 0. Linear head, one thread per batch.
    if (j < MM && b0 + j < B) {
        float s = b_lin[0];
        #pragma unroll 1
        for (int k = 0; k < HH; k++) s = fmaf(h_sh[0][j][k], W_lin[k], s);
        out[b0 + j] = s;
    }
}

extern "C" void kernel_launch(void* const* d_in, const int* in_sizes, int n_in,
                              void* d_out, int out_size) {
    const float* x     = (const float*)d_in[0];
    const float* W_ih  = (const float*)d_in[1];
    const float* W_hh  = (const float*)d_in[2];
    const float* b_ih  = (const float*)d_in[3];
    const float* b_hh  = (const float*)d_in[4];
    const float* W_lin = (const float*)d_in[5];
    const float* b_lin = (const float*)d_in[6];
    float* out = (float*)d_out;

    int B = in_sizes[0] / TT;
    int grid = (B + MM - 1) / MM;
    lstm_kernel<<<grid, BT>>>(x, W_ih, W_hh, b_ih, b_hh, W_lin, b_lin, out, B);
}

// round 5
// speedup vs baseline: 1.3454x; 1.3454x over previous
#include <cuda_runtime.h>
#include <stdint.h>

// LSTM: H=50, input dim 1, T=1024, B independent batch elements.
// One block (128 threads, 100 active) per batch element, R=2 gate rows per
// thread: thread j (<100) owns rows j and j+100.
//   threads 0..49  : rows j (i-gate),     j+100 (g-gate)
//   threads 50..99 : rows j (f-gate),     j+100 (o-gate)
// One LDS.128 of h feeds 4 FFMA2 (ratio 1:4). Weights: 52 ull = 104 regs,
// shared h via smem broadcast. Gate exchange: thread k writes
// p[k] = sig(i)*tanh(g); thread k+50 owns c[k] privately:
// c = sig(f)*c + p;  h[k] = sig(o)*tanh(c).  Two barriers/step, single h buf.
// Gate order (PyTorch): i[0:50], f[50:100], g[100:150], o[150:200].

#define HH 50
#define TT 1024
#define BT 128
#define KP 52         // H padded to multiple of 4

typedef unsigned long long ull;

__device__ __forceinline__ float sigf(float x) {
    return 1.0f / (1.0f + __expf(-x));
}
__device__ __forceinline__ float tanhfast(float x) {
    return fmaf(2.0f, sigf(2.0f * x), -1.0f);   // exact tanh via 2*sig(2x)-1
}
__device__ __forceinline__ void fma2(ull& d, ull a, ull b) {
    asm("fma.rn.f32x2 %0, %1, %2, %0;" : "+l"(d) : "l"(a), "l"(b));
}
__device__ __forceinline__ ull pack2(float lo, float hi) {
    return ((ull)__float_as_uint(hi) << 32) | (ull)__float_as_uint(lo);
}
__device__ __forceinline__ float sum2(ull a) {
    return __uint_as_float((unsigned)a) + __uint_as_float((unsigned)(a >> 32));
}

__global__ void __launch_bounds__(BT, 3)
lstm_kernel(const float* __restrict__ x,      // [B, T, 1]
            const float* __restrict__ W_ih,   // [200, 1]
            const float* __restrict__ W_hh,   // [200, 50]
            const float* __restrict__ b_ih,   // [200]
            const float* __restrict__ b_hh,   // [200]
            const float* __restrict__ W_lin,  // [1, 50]
            const float* __restrict__ b_lin,  // [1]
            float* __restrict__ out)          // [B, 1]
{
    __shared__ __align__(16) float h_sh[KP];
    __shared__ float p_sh[HH];                // sig(i)*tanh(g) handoff
    __shared__ float x_sh[TT];

    const int j = threadIdx.x;
    const int b = blockIdx.x;
    const bool act  = (j < 100);
    const bool low  = (j < 50);               // i/g thread
    const int  k    = low ? j : j - 50;       // hidden index (for phase 2)

    for (int i = j; i < TT; i += BT) x_sh[i] = x[(size_t)b * TT + i];
    if (j < KP) h_sh[j] = 0.0f;               // h0 = 0; padding stays 0

    // Two gate rows per thread: row0 = j, row1 = j + 100.
    ull  wp[2][KP / 2];
    float wih0 = 0.0f, wih1 = 0.0f, bias0 = 0.0f, bias1 = 0.0f;
    if (act) {
        const int r0 = j, r1 = j + 100;
        wih0  = W_ih[r0];            wih1  = W_ih[r1];
        bias0 = b_ih[r0] + b_hh[r0]; bias1 = b_ih[r1] + b_hh[r1];
        #pragma unroll
        for (int q = 0; q < KP / 2; q++) {
            float l0 = (2 * q     < HH) ? W_hh[r0 * HH + 2 * q]     : 0.0f;
            float h0 = (2 * q + 1 < HH) ? W_hh[r0 * HH + 2 * q + 1] : 0.0f;
            float l1 = (2 * q     < HH) ? W_hh[r1 * HH + 2 * q]     : 0.0f;
            float h1 = (2 * q + 1 < HH) ? W_hh[r1 * HH + 2 * q + 1] : 0.0f;
            wp[0][q] = pack2(l0, h0);
            wp[1][q] = pack2(l1, h1);
        }
    }
    float c = 0.0f;                           // owned by threads 50..99
    __syncthreads();

    #pragma unroll 1
    for (int t = 0; t < TT; t++) {
        float act0 = 0.0f, act1 = 0.0f;
        if (act) {
            const float xt = x_sh[t];
            ull a00 = (ull)__float_as_uint(fmaf(xt, wih0, bias0)), a01 = 0ull;
            ull a10 = (ull)__float_as_uint(fmaf(xt, wih1, bias1)), a11 = 0ull;
            const ulonglong2* h2 = (const ulonglong2*)h_sh;
            #pragma unroll
            for (int q = 0; q < 13; q++) {
                ulonglong2 hv = h2[q];                // broadcast LDS.128
                fma2(a00, wp[0][2 * q],     hv.x);
                fma2(a01, wp[0][2 * q + 1], hv.y);
                fma2(a10, wp[1][2 * q],     hv.x);
                fma2(a11, wp[1][2 * q + 1], hv.y);
            }
            const float s0 = sum2(a00) + sum2(a01);   // i or f
            const float s1 = sum2(a10) + sum2(a11);   // g or o
            act0 = sigf(s0);
            act1 = low ? tanhfast(s1) : sigf(s1);
            if (low) p_sh[j] = act0 * act1;           // sig(i)*tanh(g)
        }
        __syncthreads();
        if (act && !low) {
            c = fmaf(act0, c, p_sh[k]);               // sig(f)*c + i*g
            h_sh[k] = act1 * tanhfast(c);             // sig(o)*tanh(c)
        }
        __syncthreads();
    }

    if (j == 0) {
        float s = b_lin[0];
        #pragma unroll 1
        for (int q = 0; q < HH; q++) s = fmaf(h_sh[q], W_lin[q], s);
        out[b] = s;
    }
}

extern "C" void kernel_launch(void* const* d_in, const int* in_sizes, int n_in,
                              void* d_out, int out_size) {
    const float* x     = (const float*)d_in[0];
    const float* W_ih  = (const float*)d_in[1];
    const float* W_hh  = (const float*)d_in[2];
    const float* b_ih  = (const float*)d_in[3];
    const float* b_hh  = (const float*)d_in[4];
    const float* W_lin = (const float*)d_in[5];
    const float* b_lin = (const float*)d_in[6];
    float* out = (float*)d_out;

    int B = in_sizes[0] / TT;
    lstm_kernel<<<B, BT>>>(x, W_ih, W_hh, b_ih, b_hh, W_lin, b_lin, out);
}